// round 5
// baseline (speedup 1.0000x reference)
#include <cuda_runtime.h>
#include <math.h>

// ---------------- problem constants ----------------
#define PB 2
#define PN 384
#define PK 384
#define PCZ 128
#define PCOUT 128
#define PBINS 16
#define PCIN (PCZ + PBINS)   // 144

#define F_EPS 1e-8f
#define F_LNEPS 1e-5f
#define F_DMAX 10.0f

// output layout: [Z_c | Z_sem_c | Z_geo_c]
#define SZ_ZC   ((long long)PB * PK * PK * PCOUT)      // 37748736
#define OFF_SEM (SZ_ZC)
#define SZ_SEM  ((long long)PB * PK * PN * PCZ)        // 37748736
#define OFF_GEO (OFF_SEM + SZ_SEM)                     // 75497472

typedef unsigned long long u64;

// ---- packed fp32x2 FMA helpers (FFMA2 — PTX-only, ptxas won't auto-fuse) ----
__device__ __forceinline__ u64 bcast2(float x) {
    u64 r; asm("mov.b64 %0, {%1, %1};" : "=l"(r) : "f"(x)); return r;
}
__device__ __forceinline__ void unpack2(u64 v, float& lo, float& hi) {
    asm("mov.b64 {%0, %1}, %2;" : "=f"(lo), "=f"(hi) : "l"(v));
}
__device__ __forceinline__ void ffma2(u64& d, u64 a, u64 b) {
    asm("fma.rn.f32x2 %0, %1, %2, %0;" : "+l"(d) : "l"(a), "l"(b));
}

// scratch reductions
__device__ float g_s[PB * PN];    // s[b,n] = mf[b,n] * sum_k A[b,n,k]
__device__ float g_col[PB * PK];  // col[b,a] = sum_n A[b,n,a]*mf[b,n]

// ---------------- K0: row/col reductions ----------------
__global__ void reduce_kernel(const float* __restrict__ A,
                              const float* __restrict__ mask_f) {
    int b = blockIdx.x;
    int t = threadIdx.x;  // 0..383
    if (blockIdx.y == 0) {
        const float* row = A + ((long long)b * PN + t) * PK;
        float s = 0.f;
        for (int k = 0; k < PK; ++k) s += row[k];
        g_s[b * PN + t] = s * mask_f[b * PN + t];
    } else {
        float s = 0.f;
        for (int n = 0; n < PN; ++n)
            s += A[((long long)b * PN + n) * PK + t] * mask_f[b * PN + n];
        g_col[b * PK + t] = s;
    }
}

// ---------------- K1: semantic-coarsening GEMM + epilogue ----------------
// C[a, m*128+z] = sum_n (A[b,n,a]*mf[n]^2) * Z[b,n,m,z]
// Z_sem[b,a,m,z] = C * mf[m]*s[m] / max(col[a]*s[m], EPS)
// grid: (m=384, aBlk=3, b=2); 256 threads; BM=BN=128, BK=16, 8x8/thread (packed f32x2)
__global__ __launch_bounds__(256, 2) void sem_gemm(
    const float* __restrict__ A, const float* __restrict__ Z,
    const float* __restrict__ mask_f, float* __restrict__ out) {
    __shared__ float sA[16 * 132];
    __shared__ float sB[16 * 128];

    const int m    = blockIdx.x;
    const int aBlk = blockIdx.y;
    const int b    = blockIdx.z;
    const int tid  = threadIdx.x;
    const int tx   = tid & 15, ty = tid >> 4;

    const float* Ab  = A + (long long)b * PN * PK + aBlk * 128;
    const float* Zb  = Z + (long long)b * PN * PN * PCZ + (long long)m * PCZ;
    const float* mfb = mask_f + b * PN;

    u64 acc[8][4];
#pragma unroll
    for (int i = 0; i < 8; ++i)
#pragma unroll
        for (int j = 0; j < 4; ++j) acc[i][j] = 0ull;

    for (int k0 = 0; k0 < PK; k0 += 16) {
        // A tile: row k=ty, cols a = tx*8..+7 ; fold mf^2
        {
            float mf  = mfb[k0 + ty];
            float mf2 = mf * mf;
            const float* p = Ab + (long long)(k0 + ty) * PK + tx * 8;
            float4 v0 = *(const float4*)p;
            float4 v1 = *(const float4*)(p + 4);
            v0.x *= mf2; v0.y *= mf2; v0.z *= mf2; v0.w *= mf2;
            v1.x *= mf2; v1.y *= mf2; v1.z *= mf2; v1.w *= mf2;
            float* d = &sA[ty * 132 + tx * 8];
            *(float4*)d = v0; *(float4*)(d + 4) = v1;
        }
        // B tile: row k=ty, cols z = tx*8..+7
        {
            const float* p = Zb + (long long)(k0 + ty) * (PN * PCZ) + tx * 8;
            float4 v0 = *(const float4*)p;
            float4 v1 = *(const float4*)(p + 4);
            float* d = &sB[ty * 128 + tx * 8];
            *(float4*)d = v0; *(float4*)(d + 4) = v1;
        }
        __syncthreads();
#pragma unroll
        for (int kt = 0; kt < 16; ++kt) {
            float4 a0 = *(const float4*)&sA[kt * 132 + ty * 8];
            float4 a1 = *(const float4*)&sA[kt * 132 + ty * 8 + 4];
            const u64* bp = (const u64*)&sB[kt * 128 + tx * 8];
            u64 bv[4] = {bp[0], bp[1], bp[2], bp[3]};
            u64 av[8];
            av[0] = bcast2(a0.x); av[1] = bcast2(a0.y);
            av[2] = bcast2(a0.z); av[3] = bcast2(a0.w);
            av[4] = bcast2(a1.x); av[5] = bcast2(a1.y);
            av[6] = bcast2(a1.z); av[7] = bcast2(a1.w);
#pragma unroll
            for (int i = 0; i < 8; ++i)
#pragma unroll
                for (int j = 0; j < 4; ++j) ffma2(acc[i][j], av[i], bv[j]);
        }
        __syncthreads();
    }

    // epilogue
    float sm  = g_s[b * PN + m];
    float num = mfb[m] * sm;
#pragma unroll
    for (int i = 0; i < 8; ++i) {
        int a = aBlk * 128 + ty * 8 + i;
        float f = num / fmaxf(g_col[b * PK + a] * sm, F_EPS);
        float* dst = out + OFF_SEM + (((long long)b * PK + a) * PN + m) * PCZ + tx * 8;
        float c[8];
        unpack2(acc[i][0], c[0], c[1]);
        unpack2(acc[i][1], c[2], c[3]);
        unpack2(acc[i][2], c[4], c[5]);
        unpack2(acc[i][3], c[6], c[7]);
        float4 o0, o1;
        o0.x = c[0] * f; o0.y = c[1] * f; o0.z = c[2] * f; o0.w = c[3] * f;
        o1.x = c[4] * f; o1.y = c[5] * f; o1.z = c[6] * f; o1.w = c[7] * f;
        *(float4*)dst = o0; *(float4*)(dst + 4) = o1;
    }
}

// ---------------- K2: geometry RBF ----------------
__global__ void geo_kernel(const float* __restrict__ mu,
                           const float* __restrict__ mask_c,
                           float* __restrict__ out) {
    int idx = blockIdx.x * 256 + threadIdx.x;
    if (idx >= PB * PK * PK) return;
    int b = idx / (PK * PK);
    int r = idx - b * PK * PK;
    int i = r / PK, j = r - i * PK;
    const float* mi = mu + ((long long)b * PK + i) * 3;
    const float* mj = mu + ((long long)b * PK + j) * 3;
    float dx = mi[0] - mj[0], dy = mi[1] - mj[1], dz = mi[2] - mj[2];
    float d = sqrtf(dx * dx + dy * dy + dz * dz + F_EPS);
    float mc2 = mask_c[b * PK + i] * mask_c[b * PK + j];
    const float width = F_DMAX / (PBINS - 1);
    const float invw  = (PBINS - 1) / F_DMAX;
    float* dst = out + OFF_GEO + (long long)idx * PBINS;
#pragma unroll
    for (int t = 0; t < PBINS; t += 4) {
        float4 v;
        float u;
        u = (d - (t + 0) * width) * invw; v.x = __expf(-0.5f * u * u) * mc2;
        u = (d - (t + 1) * width) * invw; v.y = __expf(-0.5f * u * u) * mc2;
        u = (d - (t + 2) * width) * invw; v.z = __expf(-0.5f * u * u) * mc2;
        u = (d - (t + 3) * width) * invw; v.w = __expf(-0.5f * u * u) * mc2;
        *(float4*)(dst + t) = v;
    }
}

// ---------------- K3: fused MLP: Linear->LN->SiLU->Linear (+mask) ----------------
// One block = 128 rows x all 128 cols. h lives in shared (sG).
// sG row stride multiple of 4 floats (float4 staging) -> 132.
#define SG_STRIDE 132
#define SMEM_MLP_FLOATS (16 * 132 + 16 * 128 + 128 * SG_STRIDE)
__global__ __launch_bounds__(256, 2) void mlp_kernel(
    float* __restrict__ out,
    const float* __restrict__ W1, const float* __restrict__ b1,
    const float* __restrict__ lng, const float* __restrict__ lnb,
    const float* __restrict__ W2, const float* __restrict__ b2,
    const float* __restrict__ mask_c) {
    extern __shared__ float smem[];
    float* sA = smem;                       // 16 x 132, X tile (transposed: [k][r])
    float* sB = smem + 16 * 132;            // 16 x 128, weight tile
    float* sG = smem + 16 * 132 + 16 * 128; // 128 x SG_STRIDE, h / silu rows

    const int row0 = blockIdx.x * 128;
    const int tid  = threadIdx.x;
    const int tx   = tid & 15, ty = tid >> 4;
    const float* sem = out + OFF_SEM;
    const float* geo = out + OFF_GEO;

    u64 acc[8][4];
#pragma unroll
    for (int i = 0; i < 8; ++i)
#pragma unroll
        for (int j = 0; j < 4; ++j) acc[i][j] = 0ull;

    // ---- GEMM1: X[128 x 144] @ W1[144 x 128] ----
    for (int k0 = 0; k0 < PCIN; k0 += 16) {
        {
            int r  = tid >> 1;
            int kk = (tid & 1) * 8;
            float4 v0, v1;
            if (k0 < PCZ) {
                const float* p = sem + (long long)(row0 + r) * PCZ + k0 + kk;
                v0 = *(const float4*)p; v1 = *(const float4*)(p + 4);
            } else {
                const float* p = geo + (long long)(row0 + r) * PBINS + kk;
                v0 = *(const float4*)p; v1 = *(const float4*)(p + 4);
            }
            sA[(kk + 0) * 132 + r] = v0.x;
            sA[(kk + 1) * 132 + r] = v0.y;
            sA[(kk + 2) * 132 + r] = v0.z;
            sA[(kk + 3) * 132 + r] = v0.w;
            sA[(kk + 4) * 132 + r] = v1.x;
            sA[(kk + 5) * 132 + r] = v1.y;
            sA[(kk + 6) * 132 + r] = v1.z;
            sA[(kk + 7) * 132 + r] = v1.w;
        }
        {
            const float* p = W1 + (long long)(k0 + ty) * PCOUT + tx * 8;
            *(float4*)&sB[ty * 128 + tx * 8]     = *(const float4*)p;
            *(float4*)&sB[ty * 128 + tx * 8 + 4] = *(const float4*)(p + 4);
        }
        __syncthreads();
#pragma unroll
        for (int kt = 0; kt < 16; ++kt) {
            float4 a0 = *(const float4*)&sA[kt * 132 + ty * 8];
            float4 a1 = *(const float4*)&sA[kt * 132 + ty * 8 + 4];
            const u64* bp = (const u64*)&sB[kt * 128 + tx * 8];
            u64 bv[4] = {bp[0], bp[1], bp[2], bp[3]};
            u64 av[8];
            av[0] = bcast2(a0.x); av[1] = bcast2(a0.y);
            av[2] = bcast2(a0.z); av[3] = bcast2(a0.w);
            av[4] = bcast2(a1.x); av[5] = bcast2(a1.y);
            av[6] = bcast2(a1.z); av[7] = bcast2(a1.w);
#pragma unroll
            for (int i = 0; i < 8; ++i)
#pragma unroll
                for (int j = 0; j < 4; ++j) ffma2(acc[i][j], av[i], bv[j]);
        }
        __syncthreads();
    }

    // bias + stage h rows into sG
    {
        float bvv[8];
#pragma unroll
        for (int j = 0; j < 8; ++j) bvv[j] = b1[tx * 8 + j];
#pragma unroll
        for (int i = 0; i < 8; ++i) {
            float c[8];
            unpack2(acc[i][0], c[0], c[1]);
            unpack2(acc[i][1], c[2], c[3]);
            unpack2(acc[i][2], c[4], c[5]);
            unpack2(acc[i][3], c[6], c[7]);
            float* d = &sG[(ty * 8 + i) * SG_STRIDE + tx * 8];
            float4 o0, o1;
            o0.x = c[0] + bvv[0]; o0.y = c[1] + bvv[1];
            o0.z = c[2] + bvv[2]; o0.w = c[3] + bvv[3];
            o1.x = c[4] + bvv[4]; o1.y = c[5] + bvv[5];
            o1.z = c[6] + bvv[6]; o1.w = c[7] + bvv[7];
            *(float4*)d = o0; *(float4*)(d + 4) = o1;
        }
    }
    __syncthreads();

    // ---- LayerNorm + SiLU, one thread per row ----
    if (tid < 128) {
        float* g = &sG[tid * SG_STRIDE];
        float s = 0.f;
#pragma unroll 8
        for (int c = 0; c < 128; ++c) s += g[c];
        float mu = s * (1.f / 128.f);
        float vs = 0.f;
#pragma unroll 8
        for (int c = 0; c < 128; ++c) { float dd = g[c] - mu; vs = fmaf(dd, dd, vs); }
        float rstd = rsqrtf(vs * (1.f / 128.f) + F_LNEPS);
#pragma unroll 8
        for (int c = 0; c < 128; ++c) {
            float x = (g[c] - mu) * rstd * lng[c] + lnb[c];
            g[c] = x / (1.f + __expf(-x));
        }
    }

    // ---- GEMM2: silu(h)[128 x 128] @ W2[128 x 128] ----
    u64 acc2[8][4];
#pragma unroll
    for (int i = 0; i < 8; ++i)
#pragma unroll
        for (int j = 0; j < 4; ++j) acc2[i][j] = 0ull;

    for (int k0 = 0; k0 < PCOUT; k0 += 16) {
        __syncthreads();
        {
            const float* p = W2 + (long long)(k0 + ty) * PCOUT + tx * 8;
            *(float4*)&sB[ty * 128 + tx * 8]     = *(const float4*)p;
            *(float4*)&sB[ty * 128 + tx * 8 + 4] = *(const float4*)(p + 4);
        }
        __syncthreads();
#pragma unroll
        for (int kt = 0; kt < 16; ++kt) {
            const u64* bp = (const u64*)&sB[kt * 128 + tx * 8];
            u64 bv[4] = {bp[0], bp[1], bp[2], bp[3]};
            u64 av[8];
#pragma unroll
            for (int i = 0; i < 8; ++i) av[i] = bcast2(sG[(ty * 8 + i) * SG_STRIDE + k0 + kt]);
#pragma unroll
            for (int i = 0; i < 8; ++i)
#pragma unroll
                for (int j = 0; j < 4; ++j) ffma2(acc2[i][j], av[i], bv[j]);
        }
    }

    // ---- epilogue: +b2, *mc2, write Z_c ----
    float b2v[8];
#pragma unroll
    for (int j = 0; j < 8; ++j) b2v[j] = b2[tx * 8 + j];
#pragma unroll
    for (int i = 0; i < 8; ++i) {
        int r  = row0 + ty * 8 + i;
        int bb = r / (PK * PK);
        int rr = r - bb * PK * PK;
        int ii = rr / PK;
        int jj = rr - ii * PK;
        float mc2 = mask_c[bb * PK + ii] * mask_c[bb * PK + jj];
        float* dst = out + (long long)r * PCOUT + tx * 8;
        float c[8];
        unpack2(acc2[i][0], c[0], c[1]);
        unpack2(acc2[i][1], c[2], c[3]);
        unpack2(acc2[i][2], c[4], c[5]);
        unpack2(acc2[i][3], c[6], c[7]);
        float4 o0, o1;
        o0.x = (c[0] + b2v[0]) * mc2; o0.y = (c[1] + b2v[1]) * mc2;
        o0.z = (c[2] + b2v[2]) * mc2; o0.w = (c[3] + b2v[3]) * mc2;
        o1.x = (c[4] + b2v[4]) * mc2; o1.y = (c[5] + b2v[5]) * mc2;
        o1.z = (c[6] + b2v[6]) * mc2; o1.w = (c[7] + b2v[7]) * mc2;
        *(float4*)dst = o0; *(float4*)(dst + 4) = o1;
    }
}

// ---------------- launch ----------------
extern "C" void kernel_launch(void* const* d_in, const int* in_sizes, int n_in,
                              void* d_out, int out_size) {
    const float* A      = (const float*)d_in[0];
    const float* Zf     = (const float*)d_in[1];
    const float* mu     = (const float*)d_in[2];
    const float* mask_f = (const float*)d_in[3];
    const float* mask_c = (const float*)d_in[4];
    const float* W1     = (const float*)d_in[5];
    const float* b1     = (const float*)d_in[6];
    const float* lng    = (const float*)d_in[7];
    const float* lnb    = (const float*)d_in[8];
    const float* W2     = (const float*)d_in[9];
    const float* b2     = (const float*)d_in[10];
    float* out = (float*)d_out;

    const int smem_mlp = SMEM_MLP_FLOATS * (int)sizeof(float);
    cudaFuncSetAttribute(mlp_kernel, cudaFuncAttributeMaxDynamicSharedMemorySize, smem_mlp);

    reduce_kernel<<<dim3(PB, 2), PK>>>(A, mask_f);
    sem_gemm<<<dim3(PN, 3, PB), 256>>>(A, Zf, mask_f, out);
    geo_kernel<<<(PB * PK * PK + 255) / 256, 256>>>(mu, mask_c, out);
    mlp_kernel<<<PB * PK * PK / 128, 256, smem_mlp>>>(out, W1, b1, lng, lnb, W2, b2, mask_c);
}

// round 8
// speedup vs baseline: 1.1430x; 1.1430x over previous
#include <cuda_runtime.h>
#include <cstdint>
#include <math.h>

// ---------------- problem constants ----------------
#define PB 2
#define PN 384
#define PK 384
#define PCZ 128
#define PCOUT 128
#define PBINS 16
#define PCIN (PCZ + PBINS)   // 144

#define F_EPS 1e-8f
#define F_LNEPS 1e-5f
#define F_DMAX 10.0f

// output layout: [Z_c | Z_sem_c | Z_geo_c]
#define SZ_ZC   ((long long)PB * PK * PK * PCOUT)      // 37748736
#define OFF_SEM (SZ_ZC)
#define SZ_SEM  ((long long)PB * PK * PN * PCZ)        // 37748736
#define OFF_GEO (OFF_SEM + SZ_SEM)                     // 75497472

typedef unsigned long long u64;

// ---- packed fp32x2 FMA helpers (mlp) ----
__device__ __forceinline__ u64 bcast2(float x) {
    u64 r; asm("mov.b64 %0, {%1, %1};" : "=l"(r) : "f"(x)); return r;
}
__device__ __forceinline__ void unpack2(u64 v, float& lo, float& hi) {
    asm("mov.b64 {%0, %1}, %2;" : "=f"(lo), "=f"(hi) : "l"(v));
}
__device__ __forceinline__ void ffma2(u64& d, u64 a, u64 b) {
    asm("fma.rn.f32x2 %0, %1, %2, %0;" : "+l"(d) : "l"(a), "l"(b));
}

// ---- tf32 mma.sync (sm_80+ baseline feature — works on plain sm_103 target) ----
__device__ __forceinline__ void mma_tf32(float* d, const uint32_t* a, uint32_t b0, uint32_t b1) {
    asm volatile(
        "mma.sync.aligned.m16n8k8.row.col.f32.tf32.tf32.f32 "
        "{%0,%1,%2,%3}, {%4,%5,%6,%7}, {%8,%9}, {%0,%1,%2,%3};"
        : "+f"(d[0]), "+f"(d[1]), "+f"(d[2]), "+f"(d[3])
        : "r"(a[0]), "r"(a[1]), "r"(a[2]), "r"(a[3]), "r"(b0), "r"(b1));
}

// scratch reductions
__device__ float g_s[PB * PN];    // s[b,n] = mf[b,n] * sum_k A[b,n,k]
__device__ float g_col[PB * PK];  // col[b,a] = sum_n A[b,n,a]*mf[b,n]

// ---------------- K0: row/col reductions ----------------
__global__ void reduce_kernel(const float* __restrict__ A,
                              const float* __restrict__ mask_f) {
    int b = blockIdx.x;
    int t = threadIdx.x;  // 0..383
    if (blockIdx.y == 0) {
        const float* row = A + ((long long)b * PN + t) * PK;
        float s = 0.f;
        for (int k = 0; k < PK; ++k) s += row[k];
        g_s[b * PN + t] = s * mask_f[b * PN + t];
    } else {
        float s = 0.f;
        for (int n = 0; n < PN; ++n)
            s += A[((long long)b * PN + n) * PK + t] * mask_f[b * PN + n];
        g_col[b * PK + t] = s;
    }
}

// ---------------- K1: semantic-coarsening GEMM on tf32 mma.sync (hi/lo split) ----
// D[a, z] = sum_n (A[b,n,a]*mf[n]^2) * Z[b,n,m,z]; epilogue scale as before.
// grid (m=384, aBlk=3, b=2), 256 thr = 8 warps (4 M x 2 N), warp tile 32x64.
// Shared layout [k][row], stride 136 floats: staging stores AND frag loads
// are both bank-conflict-free (bank = 8*kc + g, all distinct).
#define SEM_BK 32
#define SEM_STR 136
#define SEM_SMEM_BYTES (4 * SEM_BK * SEM_STR * 4)   // 69632

__global__ __launch_bounds__(256, 2)
void sem_gemm_mma(const float* __restrict__ A, const float* __restrict__ Z,
                  const float* __restrict__ mask_f, float* __restrict__ out) {
    extern __shared__ float sm[];
    float* sAhi = sm;
    float* sAlo = sm + SEM_BK * SEM_STR;
    float* sBhi = sm + 2 * SEM_BK * SEM_STR;
    float* sBlo = sm + 3 * SEM_BK * SEM_STR;

    const int m    = blockIdx.x;
    const int aBlk = blockIdx.y;
    const int b    = blockIdx.z;
    const int tid  = threadIdx.x;
    const int w    = tid >> 5, lane = tid & 31;
    const int warpM = w >> 1, warpN = w & 1;
    const int g  = lane >> 2;   // 0..7
    const int kc = lane & 3;    // 0..3

    const float* Ab  = A + (long long)b * PN * PK + aBlk * 128;
    const float* Zb  = Z + (long long)b * PN * PN * PCZ + (long long)m * PCZ;
    const float* mfb = mask_f + b * PN;

    float acc[2][8][4];
#pragma unroll
    for (int mt = 0; mt < 2; ++mt)
#pragma unroll
        for (int nt = 0; nt < 8; ++nt)
#pragma unroll
            for (int q = 0; q < 4; ++q) acc[mt][nt][q] = 0.f;

    const int kloc = tid >> 3;  // 0..31
    const int asub = tid & 7;   // 0..7

    for (int c = 0; c < PK / SEM_BK; ++c) {
        if (c) __syncthreads();
        const int n = c * SEM_BK + kloc;
        const float mf  = mfb[n];
        const float mf2 = mf * mf;
        const float* srcA = Ab + (long long)n * PK;
        const float* srcB = Zb + (long long)n * (PN * PCZ);
#pragma unroll
        for (int j = 0; j < 16; ++j) {
            const int a = asub + 8 * j;
            float v  = srcA[a] * mf2;
            float hi = __uint_as_float(__float_as_uint(v) & 0xFFFFE000u);
            sAhi[kloc * SEM_STR + a] = hi;
            sAlo[kloc * SEM_STR + a] = v - hi;
            float vz = srcB[a];
            float hz = __uint_as_float(__float_as_uint(vz) & 0xFFFFE000u);
            sBhi[kloc * SEM_STR + a] = hz;
            sBlo[kloc * SEM_STR + a] = vz - hz;
        }
        __syncthreads();

#pragma unroll
        for (int ks = 0; ks < SEM_BK / 8; ++ks) {
            const int k0 = ks * 8;
            uint32_t ah[2][4], al[2][4];
#pragma unroll
            for (int mt = 0; mt < 2; ++mt) {
                const int r0 = warpM * 32 + mt * 16 + g;
                ah[mt][0] = __float_as_uint(sAhi[(k0 + kc) * SEM_STR + r0]);
                ah[mt][1] = __float_as_uint(sAhi[(k0 + kc) * SEM_STR + r0 + 8]);
                ah[mt][2] = __float_as_uint(sAhi[(k0 + kc + 4) * SEM_STR + r0]);
                ah[mt][3] = __float_as_uint(sAhi[(k0 + kc + 4) * SEM_STR + r0 + 8]);
                al[mt][0] = __float_as_uint(sAlo[(k0 + kc) * SEM_STR + r0]);
                al[mt][1] = __float_as_uint(sAlo[(k0 + kc) * SEM_STR + r0 + 8]);
                al[mt][2] = __float_as_uint(sAlo[(k0 + kc + 4) * SEM_STR + r0]);
                al[mt][3] = __float_as_uint(sAlo[(k0 + kc + 4) * SEM_STR + r0 + 8]);
            }
#pragma unroll
            for (int nt = 0; nt < 8; ++nt) {
                const int cc = warpN * 64 + nt * 8 + g;
                uint32_t bh0 = __float_as_uint(sBhi[(k0 + kc) * SEM_STR + cc]);
                uint32_t bh1 = __float_as_uint(sBhi[(k0 + kc + 4) * SEM_STR + cc]);
                uint32_t bl0 = __float_as_uint(sBlo[(k0 + kc) * SEM_STR + cc]);
                uint32_t bl1 = __float_as_uint(sBlo[(k0 + kc + 4) * SEM_STR + cc]);
#pragma unroll
                for (int mt = 0; mt < 2; ++mt) {
                    mma_tf32(acc[mt][nt], ah[mt], bh0, bh1);
                    mma_tf32(acc[mt][nt], ah[mt], bl0, bl1);
                    mma_tf32(acc[mt][nt], al[mt], bh0, bh1);
                }
            }
        }
    }

    // epilogue: thread (g,kc) holds rows (r, r+8), cols (2kc, 2kc+1) per tile
    const float smv = g_s[b * PN + m];
    const float num = mfb[m] * smv;
#pragma unroll
    for (int mt = 0; mt < 2; ++mt) {
        const int a0r = aBlk * 128 + warpM * 32 + mt * 16 + g;
        const int a1r = a0r + 8;
        const float f0 = num / fmaxf(g_col[b * PK + a0r] * smv, F_EPS);
        const float f1 = num / fmaxf(g_col[b * PK + a1r] * smv, F_EPS);
        float* d0 = out + OFF_SEM + (((long long)(b * PK + a0r)) * PN + m) * PCZ;
        float* d1 = out + OFF_SEM + (((long long)(b * PK + a1r)) * PN + m) * PCZ;
#pragma unroll
        for (int nt = 0; nt < 8; ++nt) {
            const int cc = warpN * 64 + nt * 8 + 2 * kc;
            float2 v0, v1;
            v0.x = acc[mt][nt][0] * f0; v0.y = acc[mt][nt][1] * f0;
            v1.x = acc[mt][nt][2] * f1; v1.y = acc[mt][nt][3] * f1;
            *(float2*)(d0 + cc) = v0;
            *(float2*)(d1 + cc) = v1;
        }
    }
}

// ---------------- K2: geometry RBF ----------------
__global__ void geo_kernel(const float* __restrict__ mu,
                           const float* __restrict__ mask_c,
                           float* __restrict__ out) {
    int idx = blockIdx.x * 256 + threadIdx.x;
    if (idx >= PB * PK * PK) return;
    int b = idx / (PK * PK);
    int r = idx - b * PK * PK;
    int i = r / PK, j = r - i * PK;
    const float* mi = mu + ((long long)b * PK + i) * 3;
    const float* mj = mu + ((long long)b * PK + j) * 3;
    float dx = mi[0] - mj[0], dy = mi[1] - mj[1], dz = mi[2] - mj[2];
    float d = sqrtf(dx * dx + dy * dy + dz * dz + F_EPS);
    float mc2 = mask_c[b * PK + i] * mask_c[b * PK + j];
    const float width = F_DMAX / (PBINS - 1);
    const float invw  = (PBINS - 1) / F_DMAX;
    float* dst = out + OFF_GEO + (long long)idx * PBINS;
#pragma unroll
    for (int t = 0; t < PBINS; t += 4) {
        float4 v;
        float u;
        u = (d - (t + 0) * width) * invw; v.x = __expf(-0.5f * u * u) * mc2;
        u = (d - (t + 1) * width) * invw; v.y = __expf(-0.5f * u * u) * mc2;
        u = (d - (t + 2) * width) * invw; v.z = __expf(-0.5f * u * u) * mc2;
        u = (d - (t + 3) * width) * invw; v.w = __expf(-0.5f * u * u) * mc2;
        *(float4*)(dst + t) = v;
    }
}

// ---------------- K3: fused MLP (FFMA2 version, unchanged) ----------------
#define SG_STRIDE 132
#define SMEM_MLP_FLOATS (16 * 132 + 16 * 128 + 128 * SG_STRIDE)
__global__ __launch_bounds__(256, 2) void mlp_kernel(
    float* __restrict__ out,
    const float* __restrict__ W1, const float* __restrict__ b1,
    const float* __restrict__ lng, const float* __restrict__ lnb,
    const float* __restrict__ W2, const float* __restrict__ b2,
    const float* __restrict__ mask_c) {
    extern __shared__ float smemf[];
    float* sA = smemf;
    float* sB = smemf + 16 * 132;
    float* sG = smemf + 16 * 132 + 16 * 128;

    const int row0 = blockIdx.x * 128;
    const int tid  = threadIdx.x;
    const int tx   = tid & 15, ty = tid >> 4;
    const float* sem = out + OFF_SEM;
    const float* geo = out + OFF_GEO;

    u64 acc[8][4];
#pragma unroll
    for (int i = 0; i < 8; ++i)
#pragma unroll
        for (int j = 0; j < 4; ++j) acc[i][j] = 0ull;

    for (int k0 = 0; k0 < PCIN; k0 += 16) {
        {
            int r  = tid >> 1;
            int kk = (tid & 1) * 8;
            float4 v0, v1;
            if (k0 < PCZ) {
                const float* p = sem + (long long)(row0 + r) * PCZ + k0 + kk;
                v0 = *(const float4*)p; v1 = *(const float4*)(p + 4);
            } else {
                const float* p = geo + (long long)(row0 + r) * PBINS + kk;
                v0 = *(const float4*)p; v1 = *(const float4*)(p + 4);
            }
            sA[(kk + 0) * 132 + r] = v0.x;
            sA[(kk + 1) * 132 + r] = v0.y;
            sA[(kk + 2) * 132 + r] = v0.z;
            sA[(kk + 3) * 132 + r] = v0.w;
            sA[(kk + 4) * 132 + r] = v1.x;
            sA[(kk + 5) * 132 + r] = v1.y;
            sA[(kk + 6) * 132 + r] = v1.z;
            sA[(kk + 7) * 132 + r] = v1.w;
        }
        {
            const float* p = W1 + (long long)(k0 + ty) * PCOUT + tx * 8;
            *(float4*)&sB[ty * 128 + tx * 8]     = *(const float4*)p;
            *(float4*)&sB[ty * 128 + tx * 8 + 4] = *(const float4*)(p + 4);
        }
        __syncthreads();
#pragma unroll
        for (int kt = 0; kt < 16; ++kt) {
            float4 a0 = *(const float4*)&sA[kt * 132 + ty * 8];
            float4 a1 = *(const float4*)&sA[kt * 132 + ty * 8 + 4];
            const u64* bp = (const u64*)&sB[kt * 128 + tx * 8];
            u64 bv[4] = {bp[0], bp[1], bp[2], bp[3]};
            u64 av[8];
            av[0] = bcast2(a0.x); av[1] = bcast2(a0.y);
            av[2] = bcast2(a0.z); av[3] = bcast2(a0.w);
            av[4] = bcast2(a1.x); av[5] = bcast2(a1.y);
            av[6] = bcast2(a1.z); av[7] = bcast2(a1.w);
#pragma unroll
            for (int i = 0; i < 8; ++i)
#pragma unroll
                for (int j = 0; j < 4; ++j) ffma2(acc[i][j], av[i], bv[j]);
        }
        __syncthreads();
    }

    {
        float bvv[8];
#pragma unroll
        for (int j = 0; j < 8; ++j) bvv[j] = b1[tx * 8 + j];
#pragma unroll
        for (int i = 0; i < 8; ++i) {
            float c[8];
            unpack2(acc[i][0], c[0], c[1]);
            unpack2(acc[i][1], c[2], c[3]);
            unpack2(acc[i][2], c[4], c[5]);
            unpack2(acc[i][3], c[6], c[7]);
            float* d = &sG[(ty * 8 + i) * SG_STRIDE + tx * 8];
            float4 o0, o1;
            o0.x = c[0] + bvv[0]; o0.y = c[1] + bvv[1];
            o0.z = c[2] + bvv[2]; o0.w = c[3] + bvv[3];
            o1.x = c[4] + bvv[4]; o1.y = c[5] + bvv[5];
            o1.z = c[6] + bvv[6]; o1.w = c[7] + bvv[7];
            *(float4*)d = o0; *(float4*)(d + 4) = o1;
        }
    }
    __syncthreads();

    if (tid < 128) {
        float* g = &sG[tid * SG_STRIDE];
        float s = 0.f;
#pragma unroll 8
        for (int c = 0; c < 128; ++c) s += g[c];
        float mu = s * (1.f / 128.f);
        float vs = 0.f;
#pragma unroll 8
        for (int c = 0; c < 128; ++c) { float dd = g[c] - mu; vs = fmaf(dd, dd, vs); }
        float rstd = rsqrtf(vs * (1.f / 128.f) + F_LNEPS);
#pragma unroll 8
        for (int c = 0; c < 128; ++c) {
            float x = (g[c] - mu) * rstd * lng[c] + lnb[c];
            g[c] = x / (1.f + __expf(-x));
        }
    }

    u64 acc2[8][4];
#pragma unroll
    for (int i = 0; i < 8; ++i)
#pragma unroll
        for (int j = 0; j < 4; ++j) acc2[i][j] = 0ull;

    for (int k0 = 0; k0 < PCOUT; k0 += 16) {
        __syncthreads();
        {
            const float* p = W2 + (long long)(k0 + ty) * PCOUT + tx * 8;
            *(float4*)&sB[ty * 128 + tx * 8]     = *(const float4*)p;
            *(float4*)&sB[ty * 128 + tx * 8 + 4] = *(const float4*)(p + 4);
        }
        __syncthreads();
#pragma unroll
        for (int kt = 0; kt < 16; ++kt) {
            const u64* bp = (const u64*)&sB[kt * 128 + tx * 8];
            u64 bv[4] = {bp[0], bp[1], bp[2], bp[3]};
            u64 av[8];
#pragma unroll
            for (int i = 0; i < 8; ++i) av[i] = bcast2(sG[(ty * 8 + i) * SG_STRIDE + k0 + kt]);
#pragma unroll
            for (int i = 0; i < 8; ++i)
#pragma unroll
                for (int j = 0; j < 4; ++j) ffma2(acc2[i][j], av[i], bv[j]);
        }
    }

    float b2v[8];
#pragma unroll
    for (int j = 0; j < 8; ++j) b2v[j] = b2[tx * 8 + j];
#pragma unroll
    for (int i = 0; i < 8; ++i) {
        int r  = row0 + ty * 8 + i;
        int bb = r / (PK * PK);
        int rr = r - bb * PK * PK;
        int ii = rr / PK;
        int jj = rr - ii * PK;
        float mc2 = mask_c[bb * PK + ii] * mask_c[bb * PK + jj];
        float* dst = out + (long long)r * PCOUT + tx * 8;
        float c[8];
        unpack2(acc2[i][0], c[0], c[1]);
        unpack2(acc2[i][1], c[2], c[3]);
        unpack2(acc2[i][2], c[4], c[5]);
        unpack2(acc2[i][3], c[6], c[7]);
        float4 o0, o1;
        o0.x = (c[0] + b2v[0]) * mc2; o0.y = (c[1] + b2v[1]) * mc2;
        o0.z = (c[2] + b2v[2]) * mc2; o0.w = (c[3] + b2v[3]) * mc2;
        o1.x = (c[4] + b2v[4]) * mc2; o1.y = (c[5] + b2v[5]) * mc2;
        o1.z = (c[6] + b2v[6]) * mc2; o1.w = (c[7] + b2v[7]) * mc2;
        *(float4*)dst = o0; *(float4*)(dst + 4) = o1;
    }
}

// ---------------- launch ----------------
extern "C" void kernel_launch(void* const* d_in, const int* in_sizes, int n_in,
                              void* d_out, int out_size) {
    const float* A      = (const float*)d_in[0];
    const float* Zf     = (const float*)d_in[1];
    const float* mu     = (const float*)d_in[2];
    const float* mask_f = (const float*)d_in[3];
    const float* mask_c = (const float*)d_in[4];
    const float* W1     = (const float*)d_in[5];
    const float* b1     = (const float*)d_in[6];
    const float* lng    = (const float*)d_in[7];
    const float* lnb    = (const float*)d_in[8];
    const float* W2     = (const float*)d_in[9];
    const float* b2     = (const float*)d_in[10];
    float* out = (float*)d_out;

    const int smem_mlp = SMEM_MLP_FLOATS * (int)sizeof(float);
    cudaFuncSetAttribute(mlp_kernel, cudaFuncAttributeMaxDynamicSharedMemorySize, smem_mlp);
    cudaFuncSetAttribute(sem_gemm_mma, cudaFuncAttributeMaxDynamicSharedMemorySize, SEM_SMEM_BYTES);

    reduce_kernel<<<dim3(PB, 2), PK>>>(A, mask_f);
    sem_gemm_mma<<<dim3(PN, 3, PB), 256, SEM_SMEM_BYTES>>>(A, Zf, mask_f, out);
    geo_kernel<<<(PB * PK * PK + 255) / 256, 256>>>(mu, mask_c, out);
    mlp_kernel<<<PB * PK * PK / 128, 256, smem_mlp>>>(out, W1, b1, lng, lnb, W2, b2, mask_c);
}

// round 12
// speedup vs baseline: 1.2444x; 1.0887x over previous
#include <cuda_runtime.h>
#include <cstdint>
#include <math.h>

// ---------------- problem constants ----------------
#define PB 2
#define PN 384
#define PK 384
#define PCZ 128
#define PCOUT 128
#define PBINS 16
#define PCIN (PCZ + PBINS)   // 144

#define F_EPS 1e-8f
#define F_LNEPS 1e-5f
#define F_DMAX 10.0f

// output layout: [Z_c | Z_sem_c | Z_geo_c]
#define SZ_ZC   ((long long)PB * PK * PK * PCOUT)      // 37748736
#define OFF_SEM (SZ_ZC)
#define SZ_SEM  ((long long)PB * PK * PN * PCZ)        // 37748736
#define OFF_GEO (OFF_SEM + SZ_SEM)                     // 75497472

// ---- tf32 mma.sync (sm_80+ baseline feature — works on plain sm_103 target) ----
__device__ __forceinline__ void mma_tf32(float* d, const uint32_t* a, uint32_t b0, uint32_t b1) {
    asm volatile(
        "mma.sync.aligned.m16n8k8.row.col.f32.tf32.tf32.f32 "
        "{%0,%1,%2,%3}, {%4,%5,%6,%7}, {%8,%9}, {%0,%1,%2,%3};"
        : "+f"(d[0]), "+f"(d[1]), "+f"(d[2]), "+f"(d[3])
        : "r"(a[0]), "r"(a[1]), "r"(a[2]), "r"(a[3]), "r"(b0), "r"(b1));
}
__device__ __forceinline__ void split_hl(float v, float& hi, float& lo) {
    hi = __uint_as_float(__float_as_uint(v) & 0xFFFFE000u);
    lo = v - hi;
}

// scratch reductions
__device__ float g_s[PB * PN];    // s[b,n] = mf[b,n] * sum_k A[b,n,k]
__device__ float g_col[PB * PK];  // col[b,a] = sum_n A[b,n,a]*mf[b,n]

// ---------------- K0: row/col reductions ----------------
__global__ void reduce_kernel(const float* __restrict__ A,
                              const float* __restrict__ mask_f) {
    int b = blockIdx.x;
    int t = threadIdx.x;  // 0..383
    if (blockIdx.y == 0) {
        const float* row = A + ((long long)b * PN + t) * PK;
        float s = 0.f;
        for (int k = 0; k < PK; ++k) s += row[k];
        g_s[b * PN + t] = s * mask_f[b * PN + t];
    } else {
        float s = 0.f;
        for (int n = 0; n < PN; ++n)
            s += A[((long long)b * PN + n) * PK + t] * mask_f[b * PN + n];
        g_col[b * PK + t] = s;
    }
}

// ---------------- K1: semantic-coarsening GEMM on tf32 mma.sync (hi/lo split) ----
#define SEM_BK 32
#define SEM_STR 136
#define SEM_SMEM_BYTES (4 * SEM_BK * SEM_STR * 4)   // 69632

__global__ __launch_bounds__(256, 2)
void sem_gemm_mma(const float* __restrict__ A, const float* __restrict__ Z,
                  const float* __restrict__ mask_f, float* __restrict__ out) {
    extern __shared__ float sm[];
    float* sAhi = sm;
    float* sAlo = sm + SEM_BK * SEM_STR;
    float* sBhi = sm + 2 * SEM_BK * SEM_STR;
    float* sBlo = sm + 3 * SEM_BK * SEM_STR;

    const int m    = blockIdx.x;
    const int aBlk = blockIdx.y;
    const int b    = blockIdx.z;
    const int tid  = threadIdx.x;
    const int w    = tid >> 5, lane = tid & 31;
    const int warpM = w >> 1, warpN = w & 1;
    const int g  = lane >> 2;
    const int kc = lane & 3;

    const float* Ab  = A + (long long)b * PN * PK + aBlk * 128;
    const float* Zb  = Z + (long long)b * PN * PN * PCZ + (long long)m * PCZ;
    const float* mfb = mask_f + b * PN;

    float acc[2][8][4];
#pragma unroll
    for (int mt = 0; mt < 2; ++mt)
#pragma unroll
        for (int nt = 0; nt < 8; ++nt)
#pragma unroll
            for (int q = 0; q < 4; ++q) acc[mt][nt][q] = 0.f;

    const int kloc = tid >> 3;
    const int asub = tid & 7;

    for (int c = 0; c < PK / SEM_BK; ++c) {
        if (c) __syncthreads();
        const int n = c * SEM_BK + kloc;
        const float mf  = mfb[n];
        const float mf2 = mf * mf;
        const float* srcA = Ab + (long long)n * PK;
        const float* srcB = Zb + (long long)n * (PN * PCZ);
#pragma unroll
        for (int j = 0; j < 16; ++j) {
            const int a = asub + 8 * j;
            float hi, lo;
            split_hl(srcA[a] * mf2, hi, lo);
            sAhi[kloc * SEM_STR + a] = hi;
            sAlo[kloc * SEM_STR + a] = lo;
            split_hl(srcB[a], hi, lo);
            sBhi[kloc * SEM_STR + a] = hi;
            sBlo[kloc * SEM_STR + a] = lo;
        }
        __syncthreads();

#pragma unroll
        for (int ks = 0; ks < SEM_BK / 8; ++ks) {
            const int k0 = ks * 8;
            uint32_t ah[2][4], al[2][4];
#pragma unroll
            for (int mt = 0; mt < 2; ++mt) {
                const int r0 = warpM * 32 + mt * 16 + g;
                ah[mt][0] = __float_as_uint(sAhi[(k0 + kc) * SEM_STR + r0]);
                ah[mt][1] = __float_as_uint(sAhi[(k0 + kc) * SEM_STR + r0 + 8]);
                ah[mt][2] = __float_as_uint(sAhi[(k0 + kc + 4) * SEM_STR + r0]);
                ah[mt][3] = __float_as_uint(sAhi[(k0 + kc + 4) * SEM_STR + r0 + 8]);
                al[mt][0] = __float_as_uint(sAlo[(k0 + kc) * SEM_STR + r0]);
                al[mt][1] = __float_as_uint(sAlo[(k0 + kc) * SEM_STR + r0 + 8]);
                al[mt][2] = __float_as_uint(sAlo[(k0 + kc + 4) * SEM_STR + r0]);
                al[mt][3] = __float_as_uint(sAlo[(k0 + kc + 4) * SEM_STR + r0 + 8]);
            }
#pragma unroll
            for (int nt = 0; nt < 8; ++nt) {
                const int cc = warpN * 64 + nt * 8 + g;
                uint32_t bh0 = __float_as_uint(sBhi[(k0 + kc) * SEM_STR + cc]);
                uint32_t bh1 = __float_as_uint(sBhi[(k0 + kc + 4) * SEM_STR + cc]);
                uint32_t bl0 = __float_as_uint(sBlo[(k0 + kc) * SEM_STR + cc]);
                uint32_t bl1 = __float_as_uint(sBlo[(k0 + kc + 4) * SEM_STR + cc]);
#pragma unroll
                for (int mt = 0; mt < 2; ++mt) {
                    mma_tf32(acc[mt][nt], ah[mt], bh0, bh1);
                    mma_tf32(acc[mt][nt], ah[mt], bl0, bl1);
                    mma_tf32(acc[mt][nt], al[mt], bh0, bh1);
                }
            }
        }
    }

    const float smv = g_s[b * PN + m];
    const float num = mfb[m] * smv;
#pragma unroll
    for (int mt = 0; mt < 2; ++mt) {
        const int a0r = aBlk * 128 + warpM * 32 + mt * 16 + g;
        const int a1r = a0r + 8;
        const float f0 = num / fmaxf(g_col[b * PK + a0r] * smv, F_EPS);
        const float f1 = num / fmaxf(g_col[b * PK + a1r] * smv, F_EPS);
        float* d0 = out + OFF_SEM + (((long long)(b * PK + a0r)) * PN + m) * PCZ;
        float* d1 = out + OFF_SEM + (((long long)(b * PK + a1r)) * PN + m) * PCZ;
#pragma unroll
        for (int nt = 0; nt < 8; ++nt) {
            const int cc = warpN * 64 + nt * 8 + 2 * kc;
            float2 v0, v1;
            v0.x = acc[mt][nt][0] * f0; v0.y = acc[mt][nt][1] * f0;
            v1.x = acc[mt][nt][2] * f1; v1.y = acc[mt][nt][3] * f1;
            *(float2*)(d0 + cc) = v0;
            *(float2*)(d1 + cc) = v1;
        }
    }
}

// ---------------- K2: geometry RBF ----------------
__global__ void geo_kernel(const float* __restrict__ mu,
                           const float* __restrict__ mask_c,
                           float* __restrict__ out) {
    int idx = blockIdx.x * 256 + threadIdx.x;
    if (idx >= PB * PK * PK) return;
    int b = idx / (PK * PK);
    int r = idx - b * PK * PK;
    int i = r / PK, j = r - i * PK;
    const float* mi = mu + ((long long)b * PK + i) * 3;
    const float* mj = mu + ((long long)b * PK + j) * 3;
    float dx = mi[0] - mj[0], dy = mi[1] - mj[1], dz = mi[2] - mj[2];
    float d = sqrtf(dx * dx + dy * dy + dz * dz + F_EPS);
    float mc2 = mask_c[b * PK + i] * mask_c[b * PK + j];
    const float width = F_DMAX / (PBINS - 1);
    const float invw  = (PBINS - 1) / F_DMAX;
    float* dst = out + OFF_GEO + (long long)idx * PBINS;
#pragma unroll
    for (int t = 0; t < PBINS; t += 4) {
        float4 v;
        float u;
        u = (d - (t + 0) * width) * invw; v.x = __expf(-0.5f * u * u) * mc2;
        u = (d - (t + 1) * width) * invw; v.y = __expf(-0.5f * u * u) * mc2;
        u = (d - (t + 2) * width) * invw; v.z = __expf(-0.5f * u * u) * mc2;
        u = (d - (t + 3) * width) * invw; v.w = __expf(-0.5f * u * u) * mc2;
        *(float4*)(dst + t) = v;
    }
}

// ---------------- K3: fused MLP on tf32 mma.sync (hi/lo split) ----------------
// One CTA = 128 rows x 128 cols; GEMM1 K=144 (9x16), LN+SiLU in sG, GEMM2 K=128 (8x16).
#define MLP_STR 136
#define MLP_CH 16
#define MLP_STAGE (MLP_CH * MLP_STR)          // 2176 floats per array
#define SG_STRIDE 132
#define SMEM_MLP_FLOATS (4 * MLP_STAGE + 128 * SG_STRIDE)   // 25600 floats = 100KB

__global__ __launch_bounds__(256, 2) void mlp_mma(
    float* __restrict__ out,
    const float* __restrict__ W1, const float* __restrict__ b1,
    const float* __restrict__ lng, const float* __restrict__ lnb,
    const float* __restrict__ W2, const float* __restrict__ b2,
    const float* __restrict__ mask_c) {
    extern __shared__ float sm[];
    float* sAhi = sm;
    float* sAlo = sm + MLP_STAGE;
    float* sBhi = sm + 2 * MLP_STAGE;
    float* sBlo = sm + 3 * MLP_STAGE;
    float* sG   = sm + 4 * MLP_STAGE;     // 128 x SG_STRIDE

    const int row0 = blockIdx.x * 128;
    const int tid  = threadIdx.x;
    const int w    = tid >> 5, lane = tid & 31;
    const int warpM = w >> 1, warpN = w & 1;
    const int g  = lane >> 2;
    const int kc = lane & 3;
    const float* sem = out + OFF_SEM;
    const float* geo = out + OFF_GEO;

    // staging thread mapping (row-coalesced load, [k][r] scatter)
    const int sr = tid >> 1;            // 0..127 row
    const int sk = (tid & 1) * 8;       // 0 or 8

    float acc[2][8][4];
#pragma unroll
    for (int mt = 0; mt < 2; ++mt)
#pragma unroll
        for (int nt = 0; nt < 8; ++nt)
#pragma unroll
            for (int q = 0; q < 4; ++q) acc[mt][nt][q] = 0.f;

    // ---- GEMM1: X[128x144] @ W1[144x128] ----
    for (int c = 0; c < PCIN / MLP_CH; ++c) {
        if (c) __syncthreads();
        // stage X (hi/lo), coalesced row read -> [k][r] scatter
        {
            const float* p = (c < 8)
                ? sem + (long long)(row0 + sr) * PCZ + c * MLP_CH + sk
                : geo + (long long)(row0 + sr) * PBINS + sk;
            float4 v0 = *(const float4*)p;
            float4 v1 = *(const float4*)(p + 4);
            float vv[8] = {v0.x, v0.y, v0.z, v0.w, v1.x, v1.y, v1.z, v1.w};
#pragma unroll
            for (int i = 0; i < 8; ++i) {
                float hi, lo;
                split_hl(vv[i], hi, lo);
                sAhi[(sk + i) * MLP_STR + sr] = hi;
                sAlo[(sk + i) * MLP_STR + sr] = lo;
            }
        }
        // stage W1 (hi/lo): ky = tid>>4 (k-row), cx = tid&15 (8 cols)
        {
            const int ky = tid >> 4, cx = tid & 15;
            const float* q = W1 + (long long)(c * MLP_CH + ky) * PCOUT + cx * 8;
            float4 v0 = *(const float4*)q;
            float4 v1 = *(const float4*)(q + 4);
            float vv[8] = {v0.x, v0.y, v0.z, v0.w, v1.x, v1.y, v1.z, v1.w};
#pragma unroll
            for (int i = 0; i < 8; ++i) {
                float hi, lo;
                split_hl(vv[i], hi, lo);
                sBhi[ky * MLP_STR + cx * 8 + i] = hi;
                sBlo[ky * MLP_STR + cx * 8 + i] = lo;
            }
        }
        __syncthreads();
#pragma unroll
        for (int ks = 0; ks < MLP_CH / 8; ++ks) {
            const int k0 = ks * 8;
            uint32_t ah[2][4], al[2][4];
#pragma unroll
            for (int mt = 0; mt < 2; ++mt) {
                const int r0 = warpM * 32 + mt * 16 + g;
                ah[mt][0] = __float_as_uint(sAhi[(k0 + kc) * MLP_STR + r0]);
                ah[mt][1] = __float_as_uint(sAhi[(k0 + kc) * MLP_STR + r0 + 8]);
                ah[mt][2] = __float_as_uint(sAhi[(k0 + kc + 4) * MLP_STR + r0]);
                ah[mt][3] = __float_as_uint(sAhi[(k0 + kc + 4) * MLP_STR + r0 + 8]);
                al[mt][0] = __float_as_uint(sAlo[(k0 + kc) * MLP_STR + r0]);
                al[mt][1] = __float_as_uint(sAlo[(k0 + kc) * MLP_STR + r0 + 8]);
                al[mt][2] = __float_as_uint(sAlo[(k0 + kc + 4) * MLP_STR + r0]);
                al[mt][3] = __float_as_uint(sAlo[(k0 + kc + 4) * MLP_STR + r0 + 8]);
            }
#pragma unroll
            for (int nt = 0; nt < 8; ++nt) {
                const int cc = warpN * 64 + nt * 8 + g;
                uint32_t bh0 = __float_as_uint(sBhi[(k0 + kc) * MLP_STR + cc]);
                uint32_t bh1 = __float_as_uint(sBhi[(k0 + kc + 4) * MLP_STR + cc]);
                uint32_t bl0 = __float_as_uint(sBlo[(k0 + kc) * MLP_STR + cc]);
                uint32_t bl1 = __float_as_uint(sBlo[(k0 + kc + 4) * MLP_STR + cc]);
#pragma unroll
                for (int mt = 0; mt < 2; ++mt) {
                    mma_tf32(acc[mt][nt], ah[mt], bh0, bh1);
                    mma_tf32(acc[mt][nt], ah[mt], bl0, bl1);
                    mma_tf32(acc[mt][nt], al[mt], bh0, bh1);
                }
            }
        }
    }
    __syncthreads();

    // ---- write h = acc + b1 into sG (fragment layout) ----
#pragma unroll
    for (int mt = 0; mt < 2; ++mt) {
        const int r0 = warpM * 32 + mt * 16 + g;
#pragma unroll
        for (int nt = 0; nt < 8; ++nt) {
            const int cc = warpN * 64 + nt * 8 + 2 * kc;
            float2 bb = *(const float2*)(b1 + cc);
            float2 v0, v1;
            v0.x = acc[mt][nt][0] + bb.x; v0.y = acc[mt][nt][1] + bb.y;
            v1.x = acc[mt][nt][2] + bb.x; v1.y = acc[mt][nt][3] + bb.y;
            *(float2*)&sG[r0 * SG_STRIDE + cc]       = v0;
            *(float2*)&sG[(r0 + 8) * SG_STRIDE + cc] = v1;
        }
    }
    __syncthreads();

    // ---- LayerNorm + SiLU, one thread per row ----
    if (tid < 128) {
        float* gr = &sG[tid * SG_STRIDE];
        float s = 0.f;
#pragma unroll 8
        for (int c = 0; c < 128; ++c) s += gr[c];
        float mu = s * (1.f / 128.f);
        float vs = 0.f;
#pragma unroll 8
        for (int c = 0; c < 128; ++c) { float dd = gr[c] - mu; vs = fmaf(dd, dd, vs); }
        float rstd = rsqrtf(vs * (1.f / 128.f) + F_LNEPS);
#pragma unroll 8
        for (int c = 0; c < 128; ++c) {
            float x = (gr[c] - mu) * rstd * lng[c] + lnb[c];
            gr[c] = x / (1.f + __expf(-x));
        }
    }
    __syncthreads();

    // ---- GEMM2: silu(h)[128x128] @ W2[128x128] ----
    float acc2[2][8][4];
#pragma unroll
    for (int mt = 0; mt < 2; ++mt)
#pragma unroll
        for (int nt = 0; nt < 8; ++nt)
#pragma unroll
            for (int q = 0; q < 4; ++q) acc2[mt][nt][q] = 0.f;

    for (int c = 0; c < PCOUT / MLP_CH; ++c) {
        if (c) __syncthreads();
        // stage A from sG (hi/lo)
        {
            const float* p = &sG[sr * SG_STRIDE + c * MLP_CH + sk];
#pragma unroll
            for (int i = 0; i < 8; ++i) {
                float hi, lo;
                split_hl(p[i], hi, lo);
                sAhi[(sk + i) * MLP_STR + sr] = hi;
                sAlo[(sk + i) * MLP_STR + sr] = lo;
            }
        }
        // stage W2 (hi/lo)
        {
            const int ky = tid >> 4, cx = tid & 15;
            const float* q = W2 + (long long)(c * MLP_CH + ky) * PCOUT + cx * 8;
            float4 v0 = *(const float4*)q;
            float4 v1 = *(const float4*)(q + 4);
            float vv[8] = {v0.x, v0.y, v0.z, v0.w, v1.x, v1.y, v1.z, v1.w};
#pragma unroll
            for (int i = 0; i < 8; ++i) {
                float hi, lo;
                split_hl(vv[i], hi, lo);
                sBhi[ky * MLP_STR + cx * 8 + i] = hi;
                sBlo[ky * MLP_STR + cx * 8 + i] = lo;
            }
        }
        __syncthreads();
#pragma unroll
        for (int ks = 0; ks < MLP_CH / 8; ++ks) {
            const int k0 = ks * 8;
            uint32_t ah[2][4], al[2][4];
#pragma unroll
            for (int mt = 0; mt < 2; ++mt) {
                const int r0 = warpM * 32 + mt * 16 + g;
                ah[mt][0] = __float_as_uint(sAhi[(k0 + kc) * MLP_STR + r0]);
                ah[mt][1] = __float_as_uint(sAhi[(k0 + kc) * MLP_STR + r0 + 8]);
                ah[mt][2] = __float_as_uint(sAhi[(k0 + kc + 4) * MLP_STR + r0]);
                ah[mt][3] = __float_as_uint(sAhi[(k0 + kc + 4) * MLP_STR + r0 + 8]);
                al[mt][0] = __float_as_uint(sAlo[(k0 + kc) * MLP_STR + r0]);
                al[mt][1] = __float_as_uint(sAlo[(k0 + kc) * MLP_STR + r0 + 8]);
                al[mt][2] = __float_as_uint(sAlo[(k0 + kc + 4) * MLP_STR + r0]);
                al[mt][3] = __float_as_uint(sAlo[(k0 + kc + 4) * MLP_STR + r0 + 8]);
            }
#pragma unroll
            for (int nt = 0; nt < 8; ++nt) {
                const int cc = warpN * 64 + nt * 8 + g;
                uint32_t bh0 = __float_as_uint(sBhi[(k0 + kc) * MLP_STR + cc]);
                uint32_t bh1 = __float_as_uint(sBhi[(k0 + kc + 4) * MLP_STR + cc]);
                uint32_t bl0 = __float_as_uint(sBlo[(k0 + kc) * MLP_STR + cc]);
                uint32_t bl1 = __float_as_uint(sBlo[(k0 + kc + 4) * MLP_STR + cc]);
#pragma unroll
                for (int mt = 0; mt < 2; ++mt) {
                    mma_tf32(acc2[mt][nt], ah[mt], bh0, bh1);
                    mma_tf32(acc2[mt][nt], ah[mt], bl0, bl1);
                    mma_tf32(acc2[mt][nt], al[mt], bh0, bh1);
                }
            }
        }
    }

    // ---- epilogue: +b2, *mc2, write Z_c ----
#pragma unroll
    for (int mt = 0; mt < 2; ++mt) {
        const int rg0 = row0 + warpM * 32 + mt * 16 + g;
        const int rg1 = rg0 + 8;
        int bb0 = rg0 / (PK * PK), rr0 = rg0 - bb0 * PK * PK;
        int bb1 = rg1 / (PK * PK), rr1 = rg1 - bb1 * PK * PK;
        int i0 = rr0 / PK, j0 = rr0 - i0 * PK;
        int i1 = rr1 / PK, j1 = rr1 - i1 * PK;
        const float mc0 = mask_c[bb0 * PK + i0] * mask_c[bb0 * PK + j0];
        const float mc1 = mask_c[bb1 * PK + i1] * mask_c[bb1 * PK + j1];
        float* d0 = out + (long long)rg0 * PCOUT;
        float* d1 = out + (long long)rg1 * PCOUT;
#pragma unroll
        for (int nt = 0; nt < 8; ++nt) {
            const int cc = warpN * 64 + nt * 8 + 2 * kc;
            float2 bb = *(const float2*)(b2 + cc);
            float2 v0, v1;
            v0.x = (acc2[mt][nt][0] + bb.x) * mc0; v0.y = (acc2[mt][nt][1] + bb.y) * mc0;
            v1.x = (acc2[mt][nt][2] + bb.x) * mc1; v1.y = (acc2[mt][nt][3] + bb.y) * mc1;
            *(float2*)(d0 + cc) = v0;
            *(float2*)(d1 + cc) = v1;
        }
    }
}

// ---------------- launch ----------------
extern "C" void kernel_launch(void* const* d_in, const int* in_sizes, int n_in,
                              void* d_out, int out_size) {
    const float* A      = (const float*)d_in[0];
    const float* Zf     = (const float*)d_in[1];
    const float* mu     = (const float*)d_in[2];
    const float* mask_f = (const float*)d_in[3];
    const float* mask_c = (const float*)d_in[4];
    const float* W1     = (const float*)d_in[5];
    const float* b1     = (const float*)d_in[6];
    const float* lng    = (const float*)d_in[7];
    const float* lnb    = (const float*)d_in[8];
    const float* W2     = (const float*)d_in[9];
    const float* b2     = (const float*)d_in[10];
    float* out = (float*)d_out;

    const int smem_mlp = SMEM_MLP_FLOATS * (int)sizeof(float);
    cudaFuncSetAttribute(mlp_mma, cudaFuncAttributeMaxDynamicSharedMemorySize, smem_mlp);
    cudaFuncSetAttribute(sem_gemm_mma, cudaFuncAttributeMaxDynamicSharedMemorySize, SEM_SMEM_BYTES);

    reduce_kernel<<<dim3(PB, 2), PK>>>(A, mask_f);
    sem_gemm_mma<<<dim3(PN, 3, PB), 256, SEM_SMEM_BYTES>>>(A, Zf, mask_f, out);
    geo_kernel<<<(PB * PK * PK + 255) / 256, 256>>>(mu, mask_c, out);
    mlp_mma<<<PB * PK * PK / 128, 256, smem_mlp>>>(out, W1, b1, lng, lnb, W2, b2, mask_c);
}